// round 13
// baseline (speedup 1.0000x reference)
#include <cuda_runtime.h>
#include <stdint.h>

// Problem constants (fixed by the dataset: B=4, H=376, W=1241, C=64)
#define BATCH   4
#define HH      376
#define WW      1241
#define CC      64
#define HW      (HH * WW)          // 466616  (divisible by 4)
#define NUM_PIX (BATCH * HW)       // 1866464
#define NPIX4   (NUM_PIX / 4)      // 466616
#define NCOL    ((NPIX4 + 31) / 32)      // 14582 columns of 32 pixel-groups
#define NSTRIPE ((NCOL + 7) / 8)         // 1823 stripes of 8 columns (1024 px)

// Scratch: packed (depth_bits<<32 | point_index) per pixel. ~14.9 MB.
__device__ unsigned long long g_keys[NUM_PIX];

// ---------------------------------------------------------------------------
// Projection matrix P = K @ R @ V2P computed inline (identical instruction
// sequence in every thread -> bitwise-identical P everywhere).
// R = [[0,-1,0],[0,0,-1],[1,0,0]]: (K@R)[i] = ( K[i][2], -K[i][0], -K[i][1] )
// ---------------------------------------------------------------------------
__device__ __forceinline__ void compute_P(const float* __restrict__ K, float* P) {
    const float vv = 0.75f;
    const float xo = 0.375f;     // 0.75/2 + 0
    const float yo = -24.625f;   // 0.75/2 - 25
    const float zo = -24.625f;   // 0.75/2 - 25
    #pragma unroll
    for (int i = 0; i < 3; i++) {
        float a =  __ldg(K + i*3 + 2);
        float b = -__ldg(K + i*3 + 0);
        float c = -__ldg(K + i*3 + 1);
        P[i*4+0] = a * vv;
        P[i*4+1] = b * vv;
        P[i*4+2] = c * vv;
        P[i*4+3] = a*xo + b*yo + c*zo;
    }
}

// ---------------------------------------------------------------------------
// Kernel 1: per-point projection + 64-bit packed atomicMin z-buffer.
// (depth_bits<<32 | index): positive-float bits are order-preserving, so one
// atomic gives min-depth with min-index tie-break, matching the reference.
// ---------------------------------------------------------------------------
__global__ void k_scatter(const int* __restrict__ coords,
                          const float* __restrict__ K, int N) {
    int i = blockIdx.x * blockDim.x + threadIdx.x;
    if (i >= N) return;

    float P[12];
    compute_P(K, P);

    int4 c = reinterpret_cast<const int4*>(coords)[i];  // (b, z, y, x)
    float x = (float)c.w;
    float y = (float)c.z;
    float z = (float)c.y;

    float p0 = fmaf(P[0], x, fmaf(P[1], y, fmaf(P[2],  z, P[3])));
    float p1 = fmaf(P[4], x, fmaf(P[5], y, fmaf(P[6],  z, P[7])));
    float d  = fmaf(P[8], x, fmaf(P[9], y, fmaf(P[10], z, P[11])));

    if (d > 1e-6f) {
        // IEEE division so floor boundaries match the fp32 reference
        int u = (int)floorf(__fdiv_rn(p0, d));
        int v = (int)floorf(__fdiv_rn(p1, d));
        if (u >= 0 && u < WW && v >= 0 && v < HH) {
            int pix = c.x * HW + v * WW + u;
            unsigned long long key =
                ((unsigned long long)__float_as_uint(d) << 32) | (unsigned int)i;
            atomicMin(&g_keys[pix], key);
        }
    }
}

// ---------------------------------------------------------------------------
// Kernel 2: fused resolve + gather (barrier-free, R11 instruction mix,
// stripe-remapped for DRAM write locality).
// blockIdx = stripe * 8 + q. One block = 1024-pixel stripe x dual channel
// quad (q, q+8): all 8 warps write the SAME two channel-quad plane sets,
// so each plane receives 4KB contiguous per block instead of an isolated
// 512B chunk -> better HBM row locality. One thread = 2 quads x 4 pixels,
// all 8 scattered LDG.128 issued up front (max per-thread MLP, as in R11).
// q==0 blocks (uniform, no warp divergence) also emit inv_depth.
// Output layout: [B*C*HW] features then [B*HW] inv_depth.
// ---------------------------------------------------------------------------
__global__ void __launch_bounds__(256)
k_gather(const float* __restrict__ feats, float* __restrict__ out) {
    int stripe = blockIdx.x >> 3;
    int cq     = blockIdx.x & 7;     // first channel quad (second = cq+8)
    int wrp    = threadIdx.x >> 5;   // column within stripe 0..7
    int gl     = threadIdx.x & 31;   // 4-pixel group within column
    int col    = stripe * 8 + wrp;
    int pg     = col * 32 + gl;      // global 4-pixel group
    if (pg >= NPIX4) return;

    const ulonglong2* kp = reinterpret_cast<const ulonglong2*>(g_keys) + 2 * pg;
    ulonglong2 ka = __ldg(kp);
    ulonglong2 kb = __ldg(kp + 1);
    // sentinel low word = 0xFFFFFFFF -> -1; winners are small non-negative.
    int w0 = (int)(unsigned)ka.x;
    int w1 = (int)(unsigned)ka.y;
    int w2 = (int)(unsigned)kb.x;
    int w3 = (int)(unsigned)kb.y;

    int p0 = pg * 4;
    int b  = p0 / HW;                // group never crosses batch (HW % 4 == 0)
    int r  = p0 - b * HW;

    if (cq == 0) {                   // block-uniform: no intra-block divergence
        float4 inv;
        inv.x = (w0 >= 0) ? __fdiv_rn(1.0f, __uint_as_float((unsigned)(ka.x >> 32))) : 0.0f;
        inv.y = (w1 >= 0) ? __fdiv_rn(1.0f, __uint_as_float((unsigned)(ka.y >> 32))) : 0.0f;
        inv.z = (w2 >= 0) ? __fdiv_rn(1.0f, __uint_as_float((unsigned)(kb.x >> 32))) : 0.0f;
        inv.w = (w3 >= 0) ? __fdiv_rn(1.0f, __uint_as_float((unsigned)(kb.y >> 32))) : 0.0f;
        __stcs(reinterpret_cast<float4*>(out + (size_t)NUM_PIX * CC) + pg, inv);
    }

    const float4 zero = make_float4(0.f, 0.f, 0.f, 0.f);
    const float4* frow0 = reinterpret_cast<const float4*>(feats + (size_t)w0 * CC);
    const float4* frow1 = reinterpret_cast<const float4*>(feats + (size_t)w1 * CC);
    const float4* frow2 = reinterpret_cast<const float4*>(feats + (size_t)w2 * CC);
    const float4* frow3 = reinterpret_cast<const float4*>(feats + (size_t)w3 * CC);

    // All 8 scattered loads issued up front -> 8 outstanding LDG.128.
    float4 fa0 = (w0 >= 0) ? __ldg(frow0 + cq)     : zero;
    float4 fa1 = (w1 >= 0) ? __ldg(frow1 + cq)     : zero;
    float4 fa2 = (w2 >= 0) ? __ldg(frow2 + cq)     : zero;
    float4 fa3 = (w3 >= 0) ? __ldg(frow3 + cq)     : zero;
    float4 fb0 = (w0 >= 0) ? __ldg(frow0 + cq + 8) : zero;
    float4 fb1 = (w1 >= 0) ? __ldg(frow1 + cq + 8) : zero;
    float4 fb2 = (w2 >= 0) ? __ldg(frow2 + cq + 8) : zero;
    float4 fb3 = (w3 >= 0) ? __ldg(frow3 + cq + 8) : zero;

    float* opa = out + (size_t)(b * CC + 4 * cq) * HW + r;
    float* opb = opa + (size_t)32 * HW;   // quad cq+8 = +32 channels

    float4 o;
    #pragma unroll
    for (int k = 0; k < 4; k++) {
        o.x = (&fa0.x)[k]; o.y = (&fa1.x)[k]; o.z = (&fa2.x)[k]; o.w = (&fa3.x)[k];
        __stcs(reinterpret_cast<float4*>(opa + (size_t)k * HW), o);
    }
    #pragma unroll
    for (int k = 0; k < 4; k++) {
        o.x = (&fb0.x)[k]; o.y = (&fb1.x)[k]; o.z = (&fb2.x)[k]; o.w = (&fb3.x)[k];
        __stcs(reinterpret_cast<float4*>(opb + (size_t)k * HW), o);
    }
}

// ---------------------------------------------------------------------------
extern "C" void kernel_launch(void* const* d_in, const int* in_sizes, int n_in,
                              void* d_out, int out_size) {
    const float* feats  = (const float*)d_in[0];   // (N, 64) f32
    const int*   coords = (const int*)d_in[1];     // (N, 4)  i32
    const float* K      = (const float*)d_in[2];   // (3, 3)  f32

    int N = in_sizes[0] / CC;
    float* out = (float*)d_out;

    // Sentinel fill via memset (0xFF bytes == all-ones keys).
    void* keys_ptr = nullptr;
    cudaGetSymbolAddress(&keys_ptr, g_keys);
    cudaMemsetAsync(keys_ptr, 0xFF, sizeof(unsigned long long) * NUM_PIX);

    const int T = 256;
    k_scatter<<<(N + T - 1) / T, T>>>(coords, K, N);

    // One block per (stripe of 8 columns) x (dual channel quad).
    k_gather<<<NSTRIPE * 8, T>>>(feats, out);
}

// round 17
// speedup vs baseline: 1.3394x; 1.3394x over previous
#include <cuda_runtime.h>
#include <stdint.h>

// Problem constants (fixed by the dataset: B=4, H=376, W=1241, C=64)
#define BATCH   4
#define HH      376
#define WW      1241
#define CC      64
#define HW      (HH * WW)          // 466616  (divisible by 4)
#define NUM_PIX (BATCH * HW)       // 1866464
#define NPIX4   (NUM_PIX / 4)      // 466616
#define NCOL    ((NPIX4 + 31) / 32)   // 14582 columns of 32 pixel-groups

// Scratch: packed (depth_bits<<32 | point_index) per pixel. ~14.9 MB.
__device__ unsigned long long g_keys[NUM_PIX];

// ---------------------------------------------------------------------------
// Projection matrix P = K @ R @ V2P computed inline (identical instruction
// sequence in every thread -> bitwise-identical P everywhere).
// R = [[0,-1,0],[0,0,-1],[1,0,0]]: (K@R)[i] = ( K[i][2], -K[i][0], -K[i][1] )
// ---------------------------------------------------------------------------
__device__ __forceinline__ void compute_P(const float* __restrict__ K, float* P) {
    const float vv = 0.75f;
    const float xo = 0.375f;     // 0.75/2 + 0
    const float yo = -24.625f;   // 0.75/2 - 25
    const float zo = -24.625f;   // 0.75/2 - 25
    #pragma unroll
    for (int i = 0; i < 3; i++) {
        float a =  __ldg(K + i*3 + 2);
        float b = -__ldg(K + i*3 + 0);
        float c = -__ldg(K + i*3 + 1);
        P[i*4+0] = a * vv;
        P[i*4+1] = b * vv;
        P[i*4+2] = c * vv;
        P[i*4+3] = a*xo + b*yo + c*zo;
    }
}

// ---------------------------------------------------------------------------
// Kernel 1: per-point projection + 64-bit packed atomicMin z-buffer.
// (depth_bits<<32 | index): positive-float bits are order-preserving, so one
// atomic gives min-depth with min-index tie-break, matching the reference.
// ---------------------------------------------------------------------------
__global__ void k_scatter(const int* __restrict__ coords,
                          const float* __restrict__ K, int N) {
    int i = blockIdx.x * blockDim.x + threadIdx.x;
    if (i >= N) return;

    float P[12];
    compute_P(K, P);

    int4 c = reinterpret_cast<const int4*>(coords)[i];  // (b, z, y, x)
    float x = (float)c.w;
    float y = (float)c.z;
    float z = (float)c.y;

    float p0 = fmaf(P[0], x, fmaf(P[1], y, fmaf(P[2],  z, P[3])));
    float p1 = fmaf(P[4], x, fmaf(P[5], y, fmaf(P[6],  z, P[7])));
    float d  = fmaf(P[8], x, fmaf(P[9], y, fmaf(P[10], z, P[11])));

    if (d > 1e-6f) {
        // IEEE division so floor boundaries match the fp32 reference
        int u = (int)floorf(__fdiv_rn(p0, d));
        int v = (int)floorf(__fdiv_rn(p1, d));
        if (u >= 0 && u < WW && v >= 0 && v < HH) {
            int pix = c.x * HW + v * WW + u;
            unsigned long long key =
                ((unsigned long long)__float_as_uint(d) << 32) | (unsigned int)i;
            atomicMin(&g_keys[pix], key);
        }
    }
}

// ---------------------------------------------------------------------------
// Kernel 2: fused resolve + gather (barrier-free, R11 mapping law:
// channel variation INSIDE the block, pixel variation across blocks).
// 4 warps per 128-pixel column; one thread = FOUR channel quads
// (cq, cq+4, cq+8, cq+12) x 4 consecutive pixels, as two R11-style batches
// of 8 front-loaded scattered LDG.128 (same per-batch MLP as R11, but key
// reads + per-warp fixed cost halved again: 4 warps/column instead of 8).
// Feature 128B lines still L1-shared by the block's warps (same pixels).
// cq==0 warps also emit the inv_depth plane.
// Output layout: [B*C*HW] features then [B*HW] inv_depth.
// ---------------------------------------------------------------------------
__global__ void __launch_bounds__(256)
k_gather(const float* __restrict__ feats, float* __restrict__ out) {
    int i   = blockIdx.x * blockDim.x + threadIdx.x;
    int wid = i >> 5;
    int gl  = i & 31;
    int cq  = wid & 3;           // quads cq, cq+4, cq+8, cq+12
    int col = wid >> 2;          // column of 32 pixel-groups
    int pg  = col * 32 + gl;     // global 4-pixel group
    if (pg >= NPIX4) return;

    const ulonglong2* kp = reinterpret_cast<const ulonglong2*>(g_keys) + 2 * pg;
    ulonglong2 ka = __ldg(kp);
    ulonglong2 kb = __ldg(kp + 1);
    // sentinel low word = 0xFFFFFFFF -> -1; winners are small non-negative.
    int w0 = (int)(unsigned)ka.x;
    int w1 = (int)(unsigned)ka.y;
    int w2 = (int)(unsigned)kb.x;
    int w3 = (int)(unsigned)kb.y;

    int p0 = pg * 4;
    int b  = p0 / HW;            // group never crosses batch (HW % 4 == 0)
    int r  = p0 - b * HW;

    if (cq == 0) {
        float4 inv;
        inv.x = (w0 >= 0) ? __fdiv_rn(1.0f, __uint_as_float((unsigned)(ka.x >> 32))) : 0.0f;
        inv.y = (w1 >= 0) ? __fdiv_rn(1.0f, __uint_as_float((unsigned)(ka.y >> 32))) : 0.0f;
        inv.z = (w2 >= 0) ? __fdiv_rn(1.0f, __uint_as_float((unsigned)(kb.x >> 32))) : 0.0f;
        inv.w = (w3 >= 0) ? __fdiv_rn(1.0f, __uint_as_float((unsigned)(kb.y >> 32))) : 0.0f;
        __stcs(reinterpret_cast<float4*>(out + (size_t)NUM_PIX * CC) + pg, inv);
    }

    const float4 zero = make_float4(0.f, 0.f, 0.f, 0.f);
    const float4* frow0 = reinterpret_cast<const float4*>(feats + (size_t)w0 * CC);
    const float4* frow1 = reinterpret_cast<const float4*>(feats + (size_t)w1 * CC);
    const float4* frow2 = reinterpret_cast<const float4*>(feats + (size_t)w2 * CC);
    const float4* frow3 = reinterpret_cast<const float4*>(feats + (size_t)w3 * CC);

    float* op0 = out + (size_t)(b * CC + 4 * cq) * HW + r;

    // ---- Batch 1: quads cq, cq+8 (8 front-loaded scattered LDG.128) ----
    {
        float4 fa0 = (w0 >= 0) ? __ldg(frow0 + cq)     : zero;
        float4 fa1 = (w1 >= 0) ? __ldg(frow1 + cq)     : zero;
        float4 fa2 = (w2 >= 0) ? __ldg(frow2 + cq)     : zero;
        float4 fa3 = (w3 >= 0) ? __ldg(frow3 + cq)     : zero;
        float4 fb0 = (w0 >= 0) ? __ldg(frow0 + cq + 8) : zero;
        float4 fb1 = (w1 >= 0) ? __ldg(frow1 + cq + 8) : zero;
        float4 fb2 = (w2 >= 0) ? __ldg(frow2 + cq + 8) : zero;
        float4 fb3 = (w3 >= 0) ? __ldg(frow3 + cq + 8) : zero;

        float* opa = op0;                       // quad cq
        float* opb = op0 + (size_t)32 * HW;     // quad cq+8
        float4 o;
        #pragma unroll
        for (int k = 0; k < 4; k++) {
            o.x = (&fa0.x)[k]; o.y = (&fa1.x)[k]; o.z = (&fa2.x)[k]; o.w = (&fa3.x)[k];
            __stcs(reinterpret_cast<float4*>(opa + (size_t)k * HW), o);
        }
        #pragma unroll
        for (int k = 0; k < 4; k++) {
            o.x = (&fb0.x)[k]; o.y = (&fb1.x)[k]; o.z = (&fb2.x)[k]; o.w = (&fb3.x)[k];
            __stcs(reinterpret_cast<float4*>(opb + (size_t)k * HW), o);
        }
    }
    // ---- Batch 2: quads cq+4, cq+12 ----
    {
        float4 fa0 = (w0 >= 0) ? __ldg(frow0 + cq + 4)  : zero;
        float4 fa1 = (w1 >= 0) ? __ldg(frow1 + cq + 4)  : zero;
        float4 fa2 = (w2 >= 0) ? __ldg(frow2 + cq + 4)  : zero;
        float4 fa3 = (w3 >= 0) ? __ldg(frow3 + cq + 4)  : zero;
        float4 fb0 = (w0 >= 0) ? __ldg(frow0 + cq + 12) : zero;
        float4 fb1 = (w1 >= 0) ? __ldg(frow1 + cq + 12) : zero;
        float4 fb2 = (w2 >= 0) ? __ldg(frow2 + cq + 12) : zero;
        float4 fb3 = (w3 >= 0) ? __ldg(frow3 + cq + 12) : zero;

        float* opa = op0 + (size_t)16 * HW;     // quad cq+4
        float* opb = op0 + (size_t)48 * HW;     // quad cq+12
        float4 o;
        #pragma unroll
        for (int k = 0; k < 4; k++) {
            o.x = (&fa0.x)[k]; o.y = (&fa1.x)[k]; o.z = (&fa2.x)[k]; o.w = (&fa3.x)[k];
            __stcs(reinterpret_cast<float4*>(opa + (size_t)k * HW), o);
        }
        #pragma unroll
        for (int k = 0; k < 4; k++) {
            o.x = (&fb0.x)[k]; o.y = (&fb1.x)[k]; o.z = (&fb2.x)[k]; o.w = (&fb3.x)[k];
            __stcs(reinterpret_cast<float4*>(opb + (size_t)k * HW), o);
        }
    }
}

// ---------------------------------------------------------------------------
extern "C" void kernel_launch(void* const* d_in, const int* in_sizes, int n_in,
                              void* d_out, int out_size) {
    const float* feats  = (const float*)d_in[0];   // (N, 64) f32
    const int*   coords = (const int*)d_in[1];     // (N, 4)  i32
    const float* K      = (const float*)d_in[2];   // (3, 3)  f32

    int N = in_sizes[0] / CC;
    float* out = (float*)d_out;

    // Sentinel fill via memset (0xFF bytes == all-ones keys).
    void* keys_ptr = nullptr;
    cudaGetSymbolAddress(&keys_ptr, g_keys);
    cudaMemsetAsync(keys_ptr, 0xFF, sizeof(unsigned long long) * NUM_PIX);

    const int T = 256;
    k_scatter<<<(N + T - 1) / T, T>>>(coords, K, N);

    // 4 quad-warps per 32-group column; 8 warps (2 columns) per block.
    k_gather<<<(NCOL * 4 + 7) / 8, T>>>(feats, out);
}